// round 2
// baseline (speedup 1.0000x reference)
#include <cuda_runtime.h>
#include <cstdint>

#define N_NODES 8192
#define DDIM    512
#define E_EDGES 262144
#define ROW_WORDS (N_NODES / 32)   // 256 words per adjacency row

// ---- static device scratch (no allocations allowed) ----
__device__ float    g_q[N_NODES * DDIM];
__device__ float    g_k[N_NODES * DDIM];
__device__ float    g_v[N_NODES * DDIM];
__device__ unsigned g_adj[N_NODES * ROW_WORDS];   // 8 MB bitmap
__device__ float    g_meanv[DDIM];
__device__ int      g_i64;

// ------------------------------------------------------------------
// Zero the adjacency bitmap + meanv accumulator
__global__ void zero_kernel() {
    int idx = blockIdx.x * blockDim.x + threadIdx.x;
    const int total = N_NODES * ROW_WORDS;
    for (int i = idx; i < total; i += gridDim.x * blockDim.x) g_adj[i] = 0u;
    if (idx < DDIM) g_meanv[idx] = 0.f;
}

// ------------------------------------------------------------------
// Detect whether edge_index is int64 or int32.
// For int64 values < 2^31, every odd 32-bit word is 0. For int32 random
// values in [0,8192), 32 consecutive odd words being all-zero has
// probability ~ (1/8192)^32 ~ 0.
__global__ void detect_kernel(const unsigned* ei_raw) {
    int is64 = 1;
    for (int i = 1; i < 64; i += 2)
        if (ei_raw[i] != 0u) { is64 = 0; break; }
    g_i64 = is64;
}

// ------------------------------------------------------------------
// Scatter edges into bitmap (dedup happens for free)
__global__ void edge_kernel(const void* ei) {
    int e = blockIdx.x * blockDim.x + threadIdx.x;
    if (e >= E_EDGES) return;
    int r, c;
    if (g_i64) {
        const long long* p = (const long long*)ei;
        r = (int)p[e];
        c = (int)p[E_EDGES + e];
    } else {
        const int* p = (const int*)ei;
        r = p[e];
        c = p[E_EDGES + e];
    }
    atomicOr(&g_adj[r * ROW_WORDS + (c >> 5)], 1u << (c & 31));
}

// ------------------------------------------------------------------
// Projection GEMM: C = x @ W + b  for (q, k, v)
// BM=128, BN=64, BK=16; 256 threads; 8x4 outputs/thread.
#define BM 128
#define BN 64
#define BK 16

__global__ void __launch_bounds__(256, 2)
proj_kernel(const float* __restrict__ x,
            const float* __restrict__ Wq, const float* __restrict__ bq,
            const float* __restrict__ Wk, const float* __restrict__ bk,
            const float* __restrict__ Wv, const float* __restrict__ bv) {
    __shared__ float As[BK][BM + 4];
    __shared__ float Bs[BK][BN + 4];

    int which = blockIdx.y >> 3;        // 0=q, 1=k, 2=v (512/BN = 8 col blocks)
    int nb    = blockIdx.y & 7;
    const float* W    = (which == 0) ? Wq : (which == 1) ? Wk : Wv;
    const float* bias = (which == 0) ? bq : (which == 1) ? bk : bv;
    float*       C    = (which == 0) ? g_q : (which == 1) ? g_k : g_v;

    int m0  = blockIdx.x * BM;
    int n0  = nb * BN;
    int tid = threadIdx.x;
    int tr  = tid >> 4;    // 0..15 -> 8 rows each
    int tc  = tid & 15;    // 0..15 -> 4 cols each

    float acc[8][4];
    #pragma unroll
    for (int i = 0; i < 8; i++)
        #pragma unroll
        for (int j = 0; j < 4; j++) acc[i][j] = 0.f;

    for (int k0 = 0; k0 < DDIM; k0 += BK) {
        // A tile: 128x16 = 512 float4, 2 per thread
        #pragma unroll
        for (int it = 0; it < 2; it++) {
            int i4  = tid + 256 * it;
            int m   = i4 >> 2;
            int kk4 = (i4 & 3) << 2;
            float4 a = *(const float4*)&x[(size_t)(m0 + m) * DDIM + k0 + kk4];
            As[kk4 + 0][m] = a.x;
            As[kk4 + 1][m] = a.y;
            As[kk4 + 2][m] = a.z;
            As[kk4 + 3][m] = a.w;
        }
        // B tile: 16x64 = 256 float4, 1 per thread
        {
            int kk  = tid >> 4;
            int nn4 = (tid & 15) << 2;
            *(float4*)&Bs[kk][nn4] =
                *(const float4*)&W[(size_t)(k0 + kk) * DDIM + n0 + nn4];
        }
        __syncthreads();

        #pragma unroll
        for (int kk = 0; kk < BK; kk++) {
            float a[8], b[4];
            *(float4*)&a[0] = *(float4*)&As[kk][tr * 8];
            *(float4*)&a[4] = *(float4*)&As[kk][tr * 8 + 4];
            *(float4*)&b[0] = *(float4*)&Bs[kk][tc * 4];
            #pragma unroll
            for (int i = 0; i < 8; i++)
                #pragma unroll
                for (int j = 0; j < 4; j++)
                    acc[i][j] += a[i] * b[j];
        }
        __syncthreads();
    }

    #pragma unroll
    for (int i = 0; i < 8; i++) {
        int m = m0 + tr * 8 + i;
        #pragma unroll
        for (int j = 0; j < 4; j++) {
            int n = n0 + tc * 4 + j;
            C[(size_t)m * DDIM + n] = acc[i][j] + bias[n];
        }
    }
}

// ------------------------------------------------------------------
// mean(v) over rows (only used by degree-0 rows)
__global__ void meanv_kernel() {
    int tid = threadIdx.x;                // 256
    int b   = blockIdx.x;                 // 16 blocks x 512 rows
    float a0 = 0.f, a1 = 0.f;
    for (int i = b * 512; i < (b + 1) * 512; i++) {
        a0 += g_v[(size_t)i * DDIM + tid];
        a1 += g_v[(size_t)i * DDIM + tid + 256];
    }
    atomicAdd(&g_meanv[tid],       a0 * (1.f / N_NODES));
    atomicAdd(&g_meanv[tid + 256], a1 * (1.f / N_NODES));
}

// ------------------------------------------------------------------
// Sparse attention: one CTA per row.
#define MAXD 2048

__global__ void __launch_bounds__(256)
attn_kernel(float* __restrict__ out) {
    __shared__ float sq[DDIM];
    __shared__ int   snbr[MAXD];
    __shared__ float ssc[MAXD];
    __shared__ float sexp[MAXD];
    __shared__ int   wsum[8];

    int row  = blockIdx.x;
    int tid  = threadIdx.x;
    int wid  = tid >> 5;
    int lane = tid & 31;

    for (int d = tid; d < DDIM; d += 256)
        sq[d] = g_q[(size_t)row * DDIM + d];

    // Deterministic neighbor extraction: popcount + block exclusive scan
    unsigned word = g_adj[row * ROW_WORDS + tid];   // exactly 256 words, 256 threads
    int c = __popc(word);
    int pre = c;
    #pragma unroll
    for (int o = 1; o < 32; o <<= 1) {
        int t = __shfl_up_sync(0xffffffffu, pre, o);
        if (lane >= o) pre += t;
    }
    if (lane == 31) wsum[wid] = pre;
    __syncthreads();
    int base = 0;
    #pragma unroll
    for (int w = 0; w < 8; w++) {
        int s = wsum[w];
        if (w < wid) base += s;
    }
    int cnt_total = wsum[0] + wsum[1] + wsum[2] + wsum[3] +
                    wsum[4] + wsum[5] + wsum[6] + wsum[7];
    int off = base + pre - c;
    unsigned bb = word;
    while (bb) {
        int b = __ffs(bb) - 1;
        bb &= bb - 1;
        if (off < MAXD) snbr[off] = (tid << 5) + b;
        off++;
    }
    __syncthreads();

    int cnt = min(cnt_total, MAXD);

    if (cnt == 0) {
        out[(size_t)row * DDIM + tid]       = g_meanv[tid];
        out[(size_t)row * DDIM + tid + 256] = g_meanv[tid + 256];
        return;
    }

    // Scores: warp per neighbor, coalesced k reads (k resident in L2)
    const float scale = 0.04419417382415922f;  // 1/sqrt(512)
    for (int n = wid; n < cnt; n += 8) {
        const float* kj = g_k + (size_t)snbr[n] * DDIM;
        float a = 0.f;
        #pragma unroll
        for (int d = lane; d < DDIM; d += 32) a += sq[d] * kj[d];
        #pragma unroll
        for (int o = 16; o; o >>= 1) a += __shfl_xor_sync(0xffffffffu, a, o);
        if (lane == 0) ssc[n] = a * scale;
    }
    __syncthreads();

    // Softmax (cnt ~ 32, redundant per-thread reductions are cheap)
    float mx = -1e30f;
    for (int n = 0; n < cnt; n++) mx = fmaxf(mx, ssc[n]);
    for (int n = tid; n < cnt; n += 256) sexp[n] = __expf(ssc[n] - mx);
    __syncthreads();
    float sum = 0.f;
    for (int n = 0; n < cnt; n++) sum += sexp[n];
    float inv = 1.f / sum;

    // Output: each thread owns 2 dims; v reads coalesced (v resident in L2)
    float acc0 = 0.f, acc1 = 0.f;
    for (int n = 0; n < cnt; n++) {
        float w = sexp[n] * inv;
        const float* vj = g_v + (size_t)snbr[n] * DDIM;
        acc0 += w * vj[tid];
        acc1 += w * vj[tid + 256];
    }
    out[(size_t)row * DDIM + tid]       = acc0;
    out[(size_t)row * DDIM + tid + 256] = acc1;
}

// ------------------------------------------------------------------
extern "C" void kernel_launch(void* const* d_in, const int* in_sizes, int n_in,
                              void* d_out, int out_size) {
    const float* x  = (const float*)d_in[0];
    const void*  ei = d_in[1];
    const float* Wq = (const float*)d_in[2];
    const float* bq = (const float*)d_in[3];
    const float* Wk = (const float*)d_in[4];
    const float* bk = (const float*)d_in[5];
    const float* Wv = (const float*)d_in[6];
    const float* bv = (const float*)d_in[7];
    float* out = (float*)d_out;

    zero_kernel<<<2048, 256>>>();
    detect_kernel<<<1, 1>>>((const unsigned*)ei);
    edge_kernel<<<E_EDGES / 256, 256>>>(ei);
    proj_kernel<<<dim3(64, 24), 256>>>(x, Wq, bq, Wk, bk, Wv, bv);
    meanv_kernel<<<16, 256>>>();
    attn_kernel<<<N_NODES, 256>>>(out);
}

// round 8
// speedup vs baseline: 1.5297x; 1.5297x over previous
#include <cuda_runtime.h>
#include <cuda_bf16.h>
#include <cstdint>

#define N_NODES 8192
#define DDIM    512
#define E_EDGES 262144
#define ROW_WORDS (N_NODES / 32)

// ---- static device scratch ----
__device__ float    g_q[N_NODES * DDIM];
__device__ float    g_k[N_NODES * DDIM];
__device__ float    g_v[N_NODES * DDIM];
__device__ unsigned g_adj[N_NODES * ROW_WORDS];
__device__ float    g_meanv[DDIM];
__device__ int      g_i64;
__device__ __nv_bfloat16 g_xhi[N_NODES * DDIM];
__device__ __nv_bfloat16 g_xlo[N_NODES * DDIM];
__device__ __nv_bfloat16 g_whi[3 * DDIM * DDIM];
__device__ __nv_bfloat16 g_wlo[3 * DDIM * DDIM];

// ==================================================================
// helpers
// ==================================================================
__device__ __forceinline__ uint32_t smem_u32(const void* p) {
    return (uint32_t)__cvta_generic_to_shared((void*)p);
}
__device__ __forceinline__ uint32_t pack2bf16(__nv_bfloat16 e0, __nv_bfloat16 e1) {
    return (uint32_t)__bfloat16_as_ushort(e0) | ((uint32_t)__bfloat16_as_ushort(e1) << 16);
}
// split fp32 pair -> packed bf16 hi word + lo word
__device__ __forceinline__ void split_pair(float a, float b, uint32_t& hi, uint32_t& lo) {
    __nv_bfloat16 ha = __float2bfloat16(a), hb = __float2bfloat16(b);
    __nv_bfloat16 la = __float2bfloat16(a - __bfloat162float(ha));
    __nv_bfloat16 lb = __float2bfloat16(b - __bfloat162float(hb));
    hi = pack2bf16(ha, hb);
    lo = pack2bf16(la, lb);
}

#define CP_ASYNC16(dst, src) \
    asm volatile("cp.async.cg.shared.global [%0], [%1], 16;" :: "r"(dst), "l"(src))
#define CP_COMMIT() asm volatile("cp.async.commit_group;")
#define CP_WAIT(n)  asm volatile("cp.async.wait_group %0;" :: "n"(n))

#define LDSM_X4(r0,r1,r2,r3,addr) \
    asm volatile("ldmatrix.sync.aligned.m8n8.x4.shared.b16 {%0,%1,%2,%3}, [%4];" \
        : "=r"(r0),"=r"(r1),"=r"(r2),"=r"(r3) : "r"(addr))
#define LDSM_X4_T(r0,r1,r2,r3,addr) \
    asm volatile("ldmatrix.sync.aligned.m8n8.x4.trans.shared.b16 {%0,%1,%2,%3}, [%4];" \
        : "=r"(r0),"=r"(r1),"=r"(r2),"=r"(r3) : "r"(addr))

#define MMA16816(d, a, b0, b1) \
    asm volatile("mma.sync.aligned.m16n8k16.row.col.f32.bf16.bf16.f32 " \
        "{%0,%1,%2,%3}, {%4,%5,%6,%7}, {%8,%9}, {%0,%1,%2,%3};" \
        : "+f"((d)[0]),"+f"((d)[1]),"+f"((d)[2]),"+f"((d)[3]) \
        : "r"((a)[0]),"r"((a)[1]),"r"((a)[2]),"r"((a)[3]),"r"(b0),"r"(b1))

// ==================================================================
// small kernels
// ==================================================================
__global__ void zero_kernel() {
    int idx = blockIdx.x * blockDim.x + threadIdx.x;
    const int total = N_NODES * ROW_WORDS;
    for (int i = idx; i < total; i += gridDim.x * blockDim.x) g_adj[i] = 0u;
    if (idx < DDIM) g_meanv[idx] = 0.f;
}
__global__ void detect_kernel(const unsigned* ei_raw) {
    int is64 = 1;
    for (int i = 1; i < 64; i += 2)
        if (ei_raw[i] != 0u) { is64 = 0; break; }
    g_i64 = is64;
}
__global__ void edge_kernel(const void* ei) {
    int e = blockIdx.x * blockDim.x + threadIdx.x;
    if (e >= E_EDGES) return;
    int r, c;
    if (g_i64) {
        const long long* p = (const long long*)ei;
        r = (int)p[e]; c = (int)p[E_EDGES + e];
    } else {
        const int* p = (const int*)ei;
        r = p[e]; c = p[E_EDGES + e];
    }
    atomicOr(&g_adj[r * ROW_WORDS + (c >> 5)], 1u << (c & 31));
}
__global__ void meanv_kernel() {
    int tid = threadIdx.x;
    int b = blockIdx.x;
    float a0 = 0.f, a1 = 0.f;
    for (int i = b * 512; i < (b + 1) * 512; i++) {
        a0 += g_v[(size_t)i * DDIM + tid];
        a1 += g_v[(size_t)i * DDIM + tid + 256];
    }
    atomicAdd(&g_meanv[tid],       a0 * (1.f / N_NODES));
    atomicAdd(&g_meanv[tid + 256], a1 * (1.f / N_NODES));
}

// ---- precompute bf16 hi/lo splits ----
__global__ void split_x_kernel(const float* __restrict__ x) {
    int i = blockIdx.x * blockDim.x + threadIdx.x;   // over N*D/4
    const float4 a = ((const float4*)x)[i];
    uint32_t h0, l0, h1, l1;
    split_pair(a.x, a.y, h0, l0);
    split_pair(a.z, a.w, h1, l1);
    ((uint2*)g_xhi)[i] = make_uint2(h0, h1);
    ((uint2*)g_xlo)[i] = make_uint2(l0, l1);
}
__global__ void split_w_kernel(const float* __restrict__ Wq,
                               const float* __restrict__ Wk,
                               const float* __restrict__ Wv) {
    int i = blockIdx.x * blockDim.x + threadIdx.x;   // over 3*D*D/4
    const int per = DDIM * DDIM / 4;
    int which = i / per, r = i % per;
    const float* W = (which == 0) ? Wq : (which == 1) ? Wk : Wv;
    const float4 a = ((const float4*)W)[r];
    uint32_t h0, l0, h1, l1;
    split_pair(a.x, a.y, h0, l0);
    split_pair(a.z, a.w, h1, l1);
    ((uint2*)g_whi)[i] = make_uint2(h0, h1);
    ((uint2*)g_wlo)[i] = make_uint2(l0, l1);
}

// ==================================================================
// Projection GEMM via mma.sync bf16 (2-term split, 3 MMAs/product)
// CTA: 128x128 tile; 256 thr (8 warps of 32x64); BK=32, 2-stage cp.async.
// ==================================================================
#define AS_STRIDE 40     // 32 + 8 pad (bf16)
#define BS_STRIDE 136    // 128 + 8 pad (bf16)
#define A_TILE (128 * AS_STRIDE)           // 5120 bf16
#define B_TILE (32 * BS_STRIDE)            // 4352 bf16
#define A_OFF(s, p) ((s) * 2 * A_TILE + (p) * A_TILE)
#define B_OFF(s, p) (4 * A_TILE + (s) * 2 * B_TILE + (p) * B_TILE)
#define PSMEM_BF16 (4 * A_TILE + 4 * B_TILE)      // 37888 bf16
#define PSMEM_BYTES (PSMEM_BF16 * 2)              // 75776 B

extern __shared__ __nv_bfloat16 psm[];

__global__ void __launch_bounds__(256, 1)
proj_mma_kernel(const float* __restrict__ bq,
                const float* __restrict__ bk,
                const float* __restrict__ bv) {
    const int which = blockIdx.z;
    const float* bias = (which == 0) ? bq : (which == 1) ? bk : bv;
    float*       C    = (which == 0) ? g_q : (which == 1) ? g_k : g_v;
    const __nv_bfloat16* whi = g_whi + (size_t)which * DDIM * DDIM;
    const __nv_bfloat16* wlo = g_wlo + (size_t)which * DDIM * DDIM;

    const int m0 = blockIdx.x * 128;
    const int n0 = blockIdx.y * 128;
    const int tid = threadIdx.x, wid = tid >> 5, lane = tid & 31;
    const int wm = wid >> 1, wn = wid & 1;
    const uint32_t sbase = smem_u32(psm);

    float acc[2][8][4];
    #pragma unroll
    for (int mt = 0; mt < 2; mt++)
        #pragma unroll
        for (int nt = 0; nt < 8; nt++)
            #pragma unroll
            for (int e = 0; e < 4; e++) acc[mt][nt][e] = 0.f;

    // per-thread load coordinates (16B cp.async granules)
    const int ar = tid >> 1;                // A: two iters -> rows tid>>1, (tid+256)>>1... use i
    (void)ar;

    auto issue_stage = [&](int s, int k0) {
        const int buf = s & 1;
        // A: 128x32 bf16 per polarity = 512 granules; 2 per thread per pol
        #pragma unroll
        for (int p = 0; p < 2; p++) {
            const __nv_bfloat16* src = p ? g_xlo : g_xhi;
            #pragma unroll
            for (int it = 0; it < 2; it++) {
                int i = tid + 256 * it;
                int r = i >> 2, c8 = i & 3;
                uint32_t dst = sbase + (A_OFF(buf, p) + r * AS_STRIDE + c8 * 8) * 2;
                CP_ASYNC16(dst, src + (size_t)(m0 + r) * DDIM + k0 + c8 * 8);
            }
        }
        // B: 32x128 bf16 per polarity = 512 granules
        #pragma unroll
        for (int p = 0; p < 2; p++) {
            const __nv_bfloat16* src = p ? wlo : whi;
            #pragma unroll
            for (int it = 0; it < 2; it++) {
                int i = tid + 256 * it;
                int r = i >> 4, c8 = i & 15;
                uint32_t dst = sbase + (B_OFF(buf, p) + r * BS_STRIDE + c8 * 8) * 2;
                CP_ASYNC16(dst, src + (size_t)(k0 + r) * DDIM + n0 + c8 * 8);
            }
        }
        CP_COMMIT();
    };

    issue_stage(0, 0);

    const int NSTG = DDIM / 32;    // 16
    for (int s = 0; s < NSTG; s++) {
        if (s + 1 < NSTG) {
            issue_stage(s + 1, (s + 1) * 32);
            CP_WAIT(1);
        } else {
            CP_WAIT(0);
        }
        __syncthreads();

        const int buf = s & 1;
        const uint32_t aHiB = sbase + A_OFF(buf, 0) * 2;
        const uint32_t aLoB = sbase + A_OFF(buf, 1) * 2;
        const uint32_t bHiB = sbase + B_OFF(buf, 0) * 2;
        const uint32_t bLoB = sbase + B_OFF(buf, 1) * 2;

        #pragma unroll
        for (int kk = 0; kk < 2; kk++) {   // two k16 steps in BK=32
            uint32_t aH[2][4], aL[2][4];
            #pragma unroll
            for (int mt = 0; mt < 2; mt++) {
                uint32_t off = ((wm * 32 + mt * 16 + (lane & 15)) * AS_STRIDE
                                + kk * 16 + (lane >> 4) * 8) * 2;
                LDSM_X4(aH[mt][0], aH[mt][1], aH[mt][2], aH[mt][3], aHiB + off);
                LDSM_X4(aL[mt][0], aL[mt][1], aL[mt][2], aL[mt][3], aLoB + off);
            }
            uint32_t bH[8][2], bL[8][2];
            #pragma unroll
            for (int nt4 = 0; nt4 < 4; nt4++) {
                uint32_t off = ((kk * 16 + (lane & 15)) * BS_STRIDE
                                + wn * 64 + nt4 * 16 + (lane >> 4) * 8) * 2;
                LDSM_X4_T(bH[2 * nt4][0], bH[2 * nt4][1],
                          bH[2 * nt4 + 1][0], bH[2 * nt4 + 1][1], bHiB + off);
                LDSM_X4_T(bL[2 * nt4][0], bL[2 * nt4][1],
                          bL[2 * nt4 + 1][0], bL[2 * nt4 + 1][1], bLoB + off);
            }
            #pragma unroll
            for (int mt = 0; mt < 2; mt++)
                #pragma unroll
                for (int nt = 0; nt < 8; nt++) {
                    MMA16816(acc[mt][nt], aH[mt], bH[nt][0], bH[nt][1]);
                    MMA16816(acc[mt][nt], aH[mt], bL[nt][0], bL[nt][1]);
                    MMA16816(acc[mt][nt], aL[mt], bH[nt][0], bH[nt][1]);
                }
        }
        __syncthreads();
    }

    // ---- epilogue: bias + store ----
    #pragma unroll
    for (int mt = 0; mt < 2; mt++) {
        int r = m0 + wm * 32 + mt * 16 + (lane >> 2);
        #pragma unroll
        for (int nt = 0; nt < 8; nt++) {
            int cN = n0 + wn * 64 + nt * 8 + (lane & 3) * 2;
            float b0 = __ldg(&bias[cN]), b1 = __ldg(&bias[cN + 1]);
            float2 v0 = make_float2(acc[mt][nt][0] + b0, acc[mt][nt][1] + b1);
            float2 v1 = make_float2(acc[mt][nt][2] + b0, acc[mt][nt][3] + b1);
            *(float2*)&C[(size_t)r * DDIM + cN]        = v0;
            *(float2*)&C[(size_t)(r + 8) * DDIM + cN]  = v1;
        }
    }
}

// ==================================================================
// Sparse attention (unchanged, passing)
// ==================================================================
#define MAXD 2048

__global__ void __launch_bounds__(256)
attn_kernel(float* __restrict__ out) {
    __shared__ float sq[DDIM];
    __shared__ int   snbr[MAXD];
    __shared__ float ssc[MAXD];
    __shared__ float sexp[MAXD];
    __shared__ int   wsum[8];

    int row  = blockIdx.x;
    int tid  = threadIdx.x;
    int wid  = tid >> 5;
    int lane = tid & 31;

    for (int d = tid; d < DDIM; d += 256)
        sq[d] = g_q[(size_t)row * DDIM + d];

    unsigned word = g_adj[row * ROW_WORDS + tid];
    int c = __popc(word);
    int pre = c;
    #pragma unroll
    for (int o = 1; o < 32; o <<= 1) {
        int t = __shfl_up_sync(0xffffffffu, pre, o);
        if (lane >= o) pre += t;
    }
    if (lane == 31) wsum[wid] = pre;
    __syncthreads();
    int base = 0;
    #pragma unroll
    for (int w = 0; w < 8; w++) {
        int s = wsum[w];
        if (w < wid) base += s;
    }
    int cnt_total = wsum[0] + wsum[1] + wsum[2] + wsum[3] +
                    wsum[4] + wsum[5] + wsum[6] + wsum[7];
    int off = base + pre - c;
    unsigned bb = word;
    while (bb) {
        int b = __ffs(bb) - 1;
        bb &= bb - 1;
        if (off < MAXD) snbr[off] = (tid << 5) + b;
        off++;
    }
    __syncthreads();

    int cnt = min(cnt_total, MAXD);

    if (cnt == 0) {
        out[(size_t)row * DDIM + tid]       = g_meanv[tid];
        out[(size_t)row * DDIM + tid + 256] = g_meanv[tid + 256];
        return;
    }

    const float scale = 0.04419417382415922f;
    for (int n = wid; n < cnt; n += 8) {
        const float* kj = g_k + (size_t)snbr[n] * DDIM;
        float a = 0.f;
        #pragma unroll
        for (int d = lane; d < DDIM; d += 32) a += sq[d] * kj[d];
        #pragma unroll
        for (int o = 16; o; o >>= 1) a += __shfl_xor_sync(0xffffffffu, a, o);
        if (lane == 0) ssc[n] = a * scale;
    }
    __syncthreads();

    float mx = -1e30f;
    for (int n = 0; n < cnt; n++) mx = fmaxf(mx, ssc[n]);
    for (int n = tid; n < cnt; n += 256) sexp[n] = __expf(ssc[n] - mx);
    __syncthreads();
    float sum = 0.f;
    for (int n = 0; n < cnt; n++) sum += sexp[n];
    float inv = 1.f / sum;

    float acc0 = 0.f, acc1 = 0.f;
    for (int n = 0; n < cnt; n++) {
        float w = sexp[n] * inv;
        const float* vj = g_v + (size_t)snbr[n] * DDIM;
        acc0 += w * vj[tid];
        acc1 += w * vj[tid + 256];
    }
    out[(size_t)row * DDIM + tid]       = acc0;
    out[(size_t)row * DDIM + tid + 256] = acc1;
}

// ==================================================================
extern "C" void kernel_launch(void* const* d_in, const int* in_sizes, int n_in,
                              void* d_out, int out_size) {
    const float* x  = (const float*)d_in[0];
    const void*  ei = d_in[1];
    const float* Wq = (const float*)d_in[2];
    const float* bq = (const float*)d_in[3];
    const float* Wk = (const float*)d_in[4];
    const float* bk = (const float*)d_in[5];
    const float* Wv = (const float*)d_in[6];
    const float* bv = (const float*)d_in[7];
    float* out = (float*)d_out;

    cudaFuncSetAttribute(proj_mma_kernel,
                         cudaFuncAttributeMaxDynamicSharedMemorySize, PSMEM_BYTES);

    zero_kernel<<<2048, 256>>>();
    detect_kernel<<<1, 1>>>((const unsigned*)ei);
    edge_kernel<<<E_EDGES / 256, 256>>>(ei);
    split_x_kernel<<<(N_NODES * DDIM / 4) / 256, 256>>>(x);
    split_w_kernel<<<(3 * DDIM * DDIM / 4) / 256, 256>>>(Wq, Wk, Wv);
    proj_mma_kernel<<<dim3(64, 4, 3), 256, PSMEM_BYTES>>>(bq, bk, bv);
    meanv_kernel<<<16, 256>>>();
    attn_kernel<<<N_NODES, 256>>>(out);
}